// round 16
// baseline (speedup 1.0000x reference)
#include <cuda_runtime.h>
#include <cuda_fp16.h>
#include <math.h>
#include <stdint.h>

// Problem constants
#define Bsz  2
#define Tseq 2048
#define Cdim 2048
#define Hh   16
#define Dh   128
#define Mrows (Bsz*Tseq)   // 4096
#define SLICE ((size_t)Cdim * Cdim)

// -------- scratch (device globals; no allocation allowed) --------
__device__ __half g_q[(size_t)Mrows * Cdim];
__device__ __half g_k[(size_t)Mrows * Cdim];
__device__ __half g_v[(size_t)Mrows * Cdim];
__device__ __half g_o[(size_t)Mrows * Cdim];
__device__ __half g_xh[(size_t)Mrows * Cdim];   // fp16 x
__device__ __half g_wh[3 * SLICE];              // fp16 Wq/Wk/Wv (UNtransposed)
__device__ __half g_wto[SLICE];                 // fp16 Wo TRANSPOSED

// ============================================================================
// Helpers
// ============================================================================
__device__ __forceinline__ uint32_t smem_u32(const void* p) {
    uint32_t a;
    asm("{ .reg .u64 t; cvta.to.shared.u64 t, %1; cvt.u32.u64 %0, t; }"
        : "=r"(a) : "l"(p));
    return a;
}

#define CP16(sa, ga) \
    asm volatile("cp.async.cg.shared.global [%0], [%1], 16;" \
                 :: "r"(sa), "l"(ga) : "memory")

#define MMA_F16(c, a0, a1, a2, a3, b0, b1) \
    asm volatile("mma.sync.aligned.m16n8k16.row.col.f32.f16.f16.f32 " \
        "{%0,%1,%2,%3},{%4,%5,%6,%7},{%8,%9},{%0,%1,%2,%3};" \
        : "+f"((c)[0]), "+f"((c)[1]), "+f"((c)[2]), "+f"((c)[3]) \
        : "r"(a0), "r"(a1), "r"(a2), "r"(a3), "r"(b0), "r"(b1))

#define LDSM4(r0, r1, r2, r3, addr) \
    asm volatile("ldmatrix.sync.aligned.m8n8.x4.shared.b16 {%0,%1,%2,%3}, [%4];" \
        : "=r"(r0), "=r"(r1), "=r"(r2), "=r"(r3) : "r"(addr))

#define LDSM4T(r0, r1, r2, r3, addr) \
    asm volatile("ldmatrix.sync.aligned.m8n8.x4.trans.shared.b16 {%0,%1,%2,%3}, [%4];" \
        : "=r"(r0), "=r"(r1), "=r"(r2), "=r"(r3) : "r"(addr))

#define SW(r) ((((r) >> 2) & 1) << 2)

__device__ __forceinline__ uint32_t pack_h2(float lo, float hi) {
    __half2 h = __floats2half2_rn(lo, hi);
    return *reinterpret_cast<uint32_t*>(&h);
}

// ============================================================================
// fp32 -> fp16 conversion: x (2 slices) + Wq/Wk/Wv, one launch (z 0..4)
// ============================================================================
__global__ __launch_bounds__(256) void conv_h_k(
    const float* __restrict__ x,
    const float* __restrict__ Wq, const float* __restrict__ Wk,
    const float* __restrict__ Wv,
    __half* __restrict__ xh, __half* __restrict__ wh)
{
    const int z = blockIdx.z;
    const float* src;
    __half* dst;
    if      (z == 0) { src = x;          dst = xh; }
    else if (z == 1) { src = x + SLICE;  dst = xh + SLICE; }
    else if (z == 2) { src = Wq;         dst = wh; }
    else if (z == 3) { src = Wk;         dst = wh + SLICE; }
    else             { src = Wv;         dst = wh + 2 * SLICE; }
    size_t i = ((size_t)blockIdx.x * 256 + threadIdx.x) * 4;
    float4 v = *(const float4*)(src + i);
    *(__half2*)(dst + i)     = __floats2half2_rn(v.x, v.y);
    *(__half2*)(dst + i + 2) = __floats2half2_rn(v.z, v.w);
}

// ============================================================================
// Transpose 2048x2048 f32 -> fp16 (Wo only)
// ============================================================================
__global__ __launch_bounds__(256) void transpose_h_k(
    const float* __restrict__ in, __half* __restrict__ out)
{
    __shared__ float t[32][33];
    const int tx = threadIdx.x, ty = threadIdx.y;
    const int x = blockIdx.x * 32 + tx;
    const int y0 = blockIdx.y * 32;
#pragma unroll
    for (int i = 0; i < 32; i += 8)
        t[ty + i][tx] = in[(size_t)(y0 + ty + i) * Cdim + x];
    __syncthreads();
    const int xo = blockIdx.y * 32 + tx;
    const int yo0 = blockIdx.x * 32;
#pragma unroll
    for (int i = 0; i < 32; i += 8)
        out[(size_t)(yo0 + ty + i) * Cdim + xo] = __float2half_rn(t[tx][ty + i]);
}

// ============================================================================
// Shared GEMM tile constants: CTA 128x128, BK=64, 3-stage, 8 warps, 2 CTAs/SM
// ============================================================================
#define GBM 128
#define GBN 128
#define GBK 64
#define NST 3
#define GTH 256
#define A_U32 (GBM * GBK / 2)              // 4096
#define B_U32 4096                         // both layouts: 64x64 or 128x32 u32
#define STAGE_U32 (A_U32 + B_U32)          // 8192
#define STAGE_BYTES (STAGE_U32 * 4)        // 32768
#define GEMM_SMEM (NST * STAGE_BYTES)      // 98304

// ----------------------------------------------------------------------------
// Body A (QKV, from R14): W UNtransposed [K,N]; B-frags via ldmatrix.trans.
// ----------------------------------------------------------------------------
__device__ __forceinline__ void gemm_body_tw(
    const __half* __restrict__ A, const __half* __restrict__ W,
    const float* __restrict__ bias, __half* __restrict__ Cm,
    uint32_t smbase)
{
    const int tid  = threadIdx.x;
    const int lane = tid & 31;
    const int wid  = tid >> 5;
    const int wm   = wid >> 2;
    const int wn   = wid & 3;
    const int m0   = blockIdx.y * GBM;
    const int n0   = blockIdx.x * GBN;
    const int g    = lane >> 2;
    const int t    = lane & 3;
    const int l15  = lane & 15;

    uint32_t offA[4];
#pragma unroll
    for (int mi = 0; mi < 4; ++mi) {
        int r = wm * 64 + mi * 16 + l15;
        int c = lane >> 4;
        offA[mi] = 4u * (uint32_t)(r * 8 + ((c << 2) ^ SW(r)));
    }
    uint32_t offBT;
    {
        int p = lane >> 4;
        offBT = 4u * (uint32_t)(l15 * 8 + ((p << 2) ^ SW(l15)));
    }

    float acc[4][4][4];
#pragma unroll
    for (int mi = 0; mi < 4; ++mi)
#pragma unroll
        for (int ni = 0; ni < 4; ++ni)
#pragma unroll
            for (int x = 0; x < 4; ++x) acc[mi][ni][x] = 0.f;

    auto load_stage = [&](int s, int k0) {
        uint32_t ab = smbase + (uint32_t)s * STAGE_BYTES;
        uint32_t bb = ab + A_U32 * 4;
        const __half* Ap = A + (size_t)m0 * Cdim + k0;
        const __half* Wp = W + (size_t)k0 * Cdim + n0;
#pragma unroll
        for (int i = 0; i < 4; ++i) {          // A: 128 rows x 8 chunks
            int lin = i * GTH + tid;
            int r   = lin >> 3;
            int cu  = (lin & 7) * 4;
            uint32_t off = 4u * (uint32_t)((cu >> 3) * 1024 + r * 8 + ((cu & 7) ^ SW(r)));
            CP16(ab + off, Ap + (size_t)r * Cdim + cu * 2);
        }
#pragma unroll
        for (int i = 0; i < 4; ++i) {          // W: 64 k-rows x 16 chunks
            int lin = i * GTH + tid;
            int r   = lin >> 4;
            int cu  = (lin & 15) * 4;
            uint32_t off = 4u * (uint32_t)((cu >> 3) * 512 + r * 8 + ((cu & 7) ^ SW(r)));
            CP16(bb + off, Wp + (size_t)r * Cdim + cu * 2);
        }
    };

    load_stage(0, 0);
    asm volatile("cp.async.commit_group;" ::: "memory");
    load_stage(1, GBK);
    asm volatile("cp.async.commit_group;" ::: "memory");

    const int NIT = Cdim / GBK;            // 32
    for (int it = 0; it < NIT; ++it) {
        asm volatile("cp.async.wait_group 1;" ::: "memory");
        __syncthreads();

        const int nx = it + 2;
        if (nx < NIT) load_stage(nx % NST, nx * GBK);
        asm volatile("cp.async.commit_group;" ::: "memory");

        uint32_t abase = smbase + (uint32_t)(it % NST) * STAGE_BYTES;
        uint32_t bbase = abase + A_U32 * 4;

#pragma unroll
        for (int ks = 0; ks < 4; ++ks) {
            uint32_t a[4][4], b[2][4];
#pragma unroll
            for (int mi = 0; mi < 4; ++mi)
                LDSM4(a[mi][0], a[mi][1], a[mi][2], a[mi][3],
                      abase + ks * 4096 + offA[mi]);
#pragma unroll
            for (int j = 0; j < 2; ++j) {
                int dj = wn * 2 + j;
                LDSM4T(b[j][0], b[j][1], b[j][2], b[j][3],
                       bbase + dj * 2048 + ks * 512 + offBT);
            }
#pragma unroll
            for (int mi = 0; mi < 4; ++mi)
#pragma unroll
                for (int j = 0; j < 2; ++j) {
                    MMA_F16(acc[mi][2 * j],     a[mi][0], a[mi][1], a[mi][2], a[mi][3],
                            b[j][0], b[j][1]);
                    MMA_F16(acc[mi][2 * j + 1], a[mi][0], a[mi][1], a[mi][2], a[mi][3],
                            b[j][2], b[j][3]);
                }
        }
    }

#pragma unroll
    for (int mi = 0; mi < 4; ++mi) {
        int r0 = m0 + wm * 64 + mi * 16 + g;
#pragma unroll
        for (int ni = 0; ni < 4; ++ni) {
            int col = n0 + wn * 32 + ni * 8 + 2 * t;
            float2 bb = *(const float2*)(bias + col);
            *(__half2*)(Cm + (size_t)r0 * Cdim + col) =
                __floats2half2_rn(acc[mi][ni][0] + bb.x, acc[mi][ni][1] + bb.y);
            *(__half2*)(Cm + (size_t)(r0 + 8) * Cdim + col) =
                __floats2half2_rn(acc[mi][ni][2] + bb.x, acc[mi][ni][3] + bb.y);
        }
    }
}

// ----------------------------------------------------------------------------
// Body B (O projection, from R13): W TRANSPOSED [N,K]; B-frags via ldmatrix.
// ----------------------------------------------------------------------------
__device__ __forceinline__ void gemm_body_tr(
    const __half* __restrict__ A, const __half* __restrict__ Bt,
    const float* __restrict__ bias, float* __restrict__ Cm,
    uint32_t smbase)
{
    const int tid  = threadIdx.x;
    const int lane = tid & 31;
    const int wid  = tid >> 5;
    const int wm   = wid >> 2;
    const int wn   = wid & 3;
    const int m0   = blockIdx.y * GBM;
    const int n0   = blockIdx.x * GBN;
    const int g    = lane >> 2;
    const int t    = lane & 3;
    const int l15  = lane & 15;

    uint32_t offA[4], offB[2];
#pragma unroll
    for (int mi = 0; mi < 4; ++mi) {
        int r = wm * 64 + mi * 16 + l15;
        int c = lane >> 4;
        offA[mi] = 4u * (uint32_t)(r * 8 + ((c << 2) ^ SW(r)));
    }
#pragma unroll
    for (int nj = 0; nj < 2; ++nj) {
        int r = wn * 32 + nj * 16 + ((lane >> 4) << 3) + (lane & 7);
        int c = (lane >> 3) & 1;
        offB[nj] = 4u * (uint32_t)(r * 8 + ((c << 2) ^ SW(r)));
    }

    float acc[4][4][4];
#pragma unroll
    for (int mi = 0; mi < 4; ++mi)
#pragma unroll
        for (int ni = 0; ni < 4; ++ni)
#pragma unroll
            for (int x = 0; x < 4; ++x) acc[mi][ni][x] = 0.f;

    auto load_stage = [&](int s, int k0) {
        uint32_t ab = smbase + (uint32_t)s * STAGE_BYTES;
        uint32_t bb = ab + A_U32 * 4;
        const __half* Ap = A  + (size_t)m0 * Cdim + k0;
        const __half* Bp = Bt + (size_t)n0 * Cdim + k0;
#pragma unroll
        for (int i = 0; i < 4; ++i) {
            int lin = i * GTH + tid;
            int r   = lin >> 3;
            int cu  = (lin & 7) * 4;
            uint32_t off = 4u * (uint32_t)((cu >> 3) * 1024 + r * 8 + ((cu & 7) ^ SW(r)));
            CP16(ab + off, Ap + (size_t)r * Cdim + cu * 2);
        }
#pragma unroll
        for (int i = 0; i < 4; ++i) {
            int lin = i * GTH + tid;
            int r   = lin >> 3;
            int cu  = (lin & 7) * 4;
            uint32_t off = 4u * (uint32_t)((cu >> 3) * 1024 + r * 8 + ((cu & 7) ^ SW(r)));
            CP16(bb + off, Bp + (size_t)r * Cdim + cu * 2);
        }
    };

    load_stage(0, 0);
    asm volatile("cp.async.commit_group;" ::: "memory");
    load_stage(1, GBK);
    asm volatile("cp.async.commit_group;" ::: "memory");

    const int NIT = Cdim / GBK;            // 32
    for (int it = 0; it < NIT; ++it) {
        asm volatile("cp.async.wait_group 1;" ::: "memory");
        __syncthreads();

        const int nx = it + 2;
        if (nx < NIT) load_stage(nx % NST, nx * GBK);
        asm volatile("cp.async.commit_group;" ::: "memory");

        uint32_t abase = smbase + (uint32_t)(it % NST) * STAGE_BYTES;
        uint32_t bbase = abase + A_U32 * 4;

#pragma unroll
        for (int ks = 0; ks < 4; ++ks) {
            uint32_t a[4][4], b[2][4];
#pragma unroll
            for (int mi = 0; mi < 4; ++mi)
                LDSM4(a[mi][0], a[mi][1], a[mi][2], a[mi][3],
                      abase + ks * 4096 + offA[mi]);
#pragma unroll
            for (int nj = 0; nj < 2; ++nj)
                LDSM4(b[nj][0], b[nj][1], b[nj][2], b[nj][3],
                      bbase + ks * 4096 + offB[nj]);
#pragma unroll
            for (int mi = 0; mi < 4; ++mi)
#pragma unroll
                for (int nj = 0; nj < 2; ++nj) {
                    MMA_F16(acc[mi][2 * nj],     a[mi][0], a[mi][1], a[mi][2], a[mi][3],
                            b[nj][0], b[nj][1]);
                    MMA_F16(acc[mi][2 * nj + 1], a[mi][0], a[mi][1], a[mi][2], a[mi][3],
                            b[nj][2], b[nj][3]);
                }
        }
    }

#pragma unroll
    for (int mi = 0; mi < 4; ++mi) {
        int r0 = m0 + wm * 64 + mi * 16 + g;
#pragma unroll
        for (int ni = 0; ni < 4; ++ni) {
            int col = n0 + wn * 32 + ni * 8 + 2 * t;
            float2 bb = *(const float2*)(bias + col);
            *(float2*)(Cm + (size_t)r0 * Cdim + col) =
                make_float2(acc[mi][ni][0] + bb.x, acc[mi][ni][1] + bb.y);
            *(float2*)(Cm + (size_t)(r0 + 8) * Cdim + col) =
                make_float2(acc[mi][ni][2] + bb.x, acc[mi][ni][3] + bb.y);
        }
    }
}

__global__ __launch_bounds__(GTH, 2) void gemm_qkv_kernel(
    const __half* __restrict__ A, const __half* __restrict__ WhBase,
    const float* __restrict__ bq, const float* __restrict__ bk,
    const float* __restrict__ bv,
    __half* __restrict__ Cq, __half* __restrict__ Ck, __half* __restrict__ Cv)
{
    extern __shared__ uint32_t smu[];
    const int z = blockIdx.z;
    const __half* Wz  = WhBase + (size_t)z * SLICE;
    const float* bias = (z == 0) ? bq : (z == 1) ? bk : bv;
    __half*      Cm   = (z == 0) ? Cq : (z == 1) ? Ck : Cv;
    gemm_body_tw(A, Wz, bias, Cm, smem_u32(smu));
}

__global__ __launch_bounds__(GTH, 2) void gemm_o_kernel(
    const __half* __restrict__ A, const __half* __restrict__ Bt,
    const float* __restrict__ bias, float* __restrict__ Cm)
{
    extern __shared__ uint32_t smu[];
    gemm_body_tr(A, Bt, bias, Cm, smem_u32(smu));
}

// ============================================================================
// fp16 flash attention (R14/R15 proven): ABK=128 key tiles, hoisted Q frags,
// register P, ldmatrix.trans V, exp2 softmax, deferred l reduction.
// CTA: 128 queries, 8 warps. smem u32:
//   Q [0,8192) | K 2x8192 @8192 | V 2x8192 @24576  -> 163840 B, 1 CTA/SM
// ============================================================================
#define ABQ 128
#define ABK 128
#define KS_OFF   8192
#define KS_STRIDE 8192
#define VS_OFF   24576
#define VS_STRIDE 8192
#define ATTN_U32 (VS_OFF + 2 * VS_STRIDE)      // 40960
#define ATTN_SMEM_BYTES (ATTN_U32 * 4)         // 163840

__global__ __launch_bounds__(256, 1) void attn_mma_kernel(
    const __half* __restrict__ q, const __half* __restrict__ k,
    const __half* __restrict__ v, __half* __restrict__ o)
{
    extern __shared__ uint32_t smu[];
    const uint32_t smb = smem_u32(smu);
    const int tid  = threadIdx.x;
    const int lane = tid & 31;
    const int w    = tid >> 5;
    const int g    = lane >> 2;
    const int t    = lane & 3;
    const int l15  = lane & 15;

    const int qbase = (gridDim.x - 1 - blockIdx.x) * ABQ;   // long CTAs first
    const int h = blockIdx.y;
    const int b = blockIdx.z;
    const float LOG2E = 1.4426950408889634f;
    const float scale = 0.08838834764831845f * LOG2E;
    const float slope = exp2f(-0.5f * (float)(h + 1)) * LOG2E;
    const size_t headoff = (size_t)b * Tseq * Cdim + (size_t)h * Dh;

    // ---- Q tile: 128 rows x 64 u32 ----
    {
        const __half* qp = q + headoff + (size_t)qbase * Cdim;
#pragma unroll
        for (int l = 0; l < 8; ++l) {
            int lin = l * 256 + tid;
            int r   = lin >> 4;
            int cu  = (lin & 15) * 4;
            uint32_t off = (uint32_t)((cu >> 3) * 1024 + r * 8 + ((cu & 7) ^ SW(r)));
            CP16(smb + 4u * off, qp + (size_t)r * Cdim + cu * 2);
        }
    }

    const int ntiles = (qbase >> 7) + 1;   // 128-key tiles, diagonal inclusive

    auto loadKV = [&](int s, int kb) {
        const __half* kp = k + headoff + (size_t)kb * Cdim;
        const __half* vp = v + headoff + (size_t)kb * Cdim;
        uint32_t kbs = smb + 4u * (uint32_t)(KS_OFF + s * KS_STRIDE);
        uint32_t vbs = smb + 4u * (uint32_t)(VS_OFF + s * VS_STRIDE);
#pragma unroll
        for (int l = 0; l < 8; ++l) {
            int lin = l * 256 + tid;
            int r   = lin >> 4;
            int cu  = (lin & 15) * 4;
            uint32_t off = 4u * (uint32_t)((cu >> 3) * 1024 + r * 8 + ((cu & 7) ^ SW(r)));
            CP16(kbs + off, kp + (size_t)r * Cdim + cu * 2);
            CP16(vbs + off, vp + (size_t)r * Cdim + cu * 2);
        }
    };
    loadKV(0, 0);
    asm volatile("cp.async.commit_group;" ::: "memory");

    uint32_t offQ;
    {
        int r = w * 16 + l15;
        int c = lane >> 4;
        offQ = 4u * (uint32_t)(r * 8 + ((c << 2) ^ SW(r)));
    }
    uint32_t offK[8];
#pragma unroll
    for (int nj = 0; nj < 8; ++nj) {
        int r = nj * 16 + ((lane >> 4) << 3) + (lane & 7);
        int c = (lane >> 3) & 1;
        offK[nj] = 4u * (uint32_t)(r * 8 + ((c << 2) ^ SW(r)));
    }
    uint32_t offV;
    {
        int p = lane >> 4;
        offV = 4u * (uint32_t)(l15 * 8 + ((p << 2) ^ SW(l15)));
    }

    asm volatile("cp.async.wait_group 0;" ::: "memory");
    __syncthreads();
    uint32_t qa[8][4];
#pragma unroll
    for (int ks = 0; ks < 8; ++ks)
        LDSM4(qa[ks][0], qa[ks][1], qa[ks][2], qa[ks][3], smb + ks * 4096 + offQ);

    float oacc[16][4];
#pragma unroll
    for (int i = 0; i < 16; ++i)
#pragma unroll
        for (int x = 0; x < 4; ++x) oacc[i][x] = 0.f;

    float mprev0 = -INFINITY, mprev1 = -INFINITY;
    float l0 = 0.f, l1 = 0.f;
    const int row0 = qbase + w * 16 + g;
    const int row1 = row0 + 8;

    for (int kt = 0; kt < ntiles; ++kt) {
        const int sk = kt & 1;
        const int kbase = kt * ABK;
        const uint32_t kbs = smb + 4u * (uint32_t)(KS_OFF + sk * KS_STRIDE);
        const uint32_t vbs = smb + 4u * (uint32_t)(VS_OFF + sk * VS_STRIDE);

        if (kt + 1 < ntiles) {
            loadKV(sk ^ 1, kbase + ABK);
            asm volatile("cp.async.commit_group;" ::: "memory");
        }

        // ---- S = Q K^T : sacc[16][4] over 128 keys ----
        float sacc[16][4];
#pragma unroll
        for (int ni = 0; ni < 16; ++ni)
#pragma unroll
            for (int x = 0; x < 4; ++x) sacc[ni][x] = 0.f;

#pragma unroll
        for (int ks = 0; ks < 8; ++ks) {
#pragma unroll
            for (int nj = 0; nj < 8; ++nj) {
                uint32_t b0, b1, b2, b3;
                LDSM4(b0, b1, b2, b3, kbs + ks * 4096 + offK[nj]);
                MMA_F16(sacc[2 * nj],     qa[ks][0], qa[ks][1], qa[ks][2], qa[ks][3], b0, b1);
                MMA_F16(sacc[2 * nj + 1], qa[ks][0], qa[ks][1], qa[ks][2], qa[ks][3], b2, b3);
            }
        }

        // ---- scale(+log2e) + ALiBi + causal; online softmax (base-2) ----
        float mt0 = -INFINITY, mt1 = -INFINITY;
#pragma unroll
        for (int ni = 0; ni < 16; ++ni) {
            int col = kbase + ni * 8 + 2 * t;
            float al0 = slope * (float)(col - (Tseq - 1));
            float al1 = slope * (float)(col + 1 - (Tseq - 1));
            float v0 = sacc[ni][0] * scale + al0;
            float v1 = sacc[ni][1] * scale + al1;
            float v2 = sacc[ni][2] * scale + al0;
            float v3 = sacc[ni][3] * scale + al1;
            if (col     > row0) v0 = -1e30f;
            if (col + 1 > row0) v1 = -1e30f;
            if (col     > row1) v2 = -1e30f;
            if (col + 1 > row1) v3 = -1e30f;
            sacc[ni][0] = v0; sacc[ni][1] = v1; sacc[ni][2] = v2; sacc[ni][3] = v3;
            mt0 = fmaxf(mt0, fmaxf(v0, v1));
            mt1 = fmaxf(mt1, fmaxf(v2, v3));
        }
        mt0 = fmaxf(mt0, __shfl_xor_sync(0xffffffffu, mt0, 1));
        mt0 = fmaxf(mt0, __shfl_xor_sync(0xffffffffu, mt0, 2));
        mt1 = fmaxf(mt1, __shfl_xor_sync(0xffffffffu, mt1, 1));
        mt1 = fmaxf(mt1, __shfl_xor_sync(0xffffffffu, mt1, 2));
        float mnew0 = fmaxf(mprev0, mt0);
        float mnew1 = fmaxf(mprev1, mt1);
        float corr0 = exp2f(mprev0 - mnew0);
        float corr1 = exp2f(mprev1 - mnew1);
        float sum0 = 0.f, sum1 = 0.f;
#pragma unroll
        for (int ni = 0; ni < 16; ++ni) {
            float p0 = exp2f(sacc[ni][0] - mnew0);
            float p1 = exp2f(sacc[ni][1] - mnew0);
            float p2 = exp2f(sacc[ni][2] - mnew1);
            float p3 = exp2f(sacc[ni][3] - mnew1);
            sum0 += p0 + p1; sum1 += p2 + p3;
            sacc[ni][0] = p0; sacc[ni][1] = p1; sacc[ni][2] = p2; sacc[ni][3] = p3;
        }
        l0 = l0 * corr0 + sum0;
        l1 = l1 * corr1 + sum1;
        mprev0 = mnew0; mprev1 = mnew1;
#pragma unroll
        for (int i = 0; i < 16; ++i) {
            oacc[i][0] *= corr0; oacc[i][1] *= corr0;
            oacc[i][2] *= corr1; oacc[i][3] *= corr1;
        }

        // ---- O += P V : 8 k16-steps over 128 keys ----
#pragma unroll
        for (int ks = 0; ks < 8; ++ks) {
            uint32_t pa0 = pack_h2(sacc[2 * ks][0],     sacc[2 * ks][1]);
            uint32_t pa1 = pack_h2(sacc[2 * ks][2],     sacc[2 * ks][3]);
            uint32_t pa2 = pack_h2(sacc[2 * ks + 1][0], sacc[2 * ks + 1][1]);
            uint32_t pa3 = pack_h2(sacc[2 * ks + 1][2], sacc[2 * ks + 1][3]);
#pragma unroll
            for (int dj = 0; dj < 8; ++dj) {
                uint32_t b0, b1, b2, b3;
                LDSM4T(b0, b1, b2, b3, vbs + dj * 4096 + ks * 512 + offV);
                MMA_F16(oacc[2 * dj],     pa0, pa1, pa2, pa3, b0, b1);
                MMA_F16(oacc[2 * dj + 1], pa0, pa1, pa2, pa3, b2, b3);
            }
        }

        if (kt + 1 < ntiles) {
            asm volatile("cp.async.wait_group 0;" ::: "memory");
            __syncthreads();
        }
    }

    // ---- epilogue: reduce deferred l, normalize, store ----
    l0 += __shfl_xor_sync(0xffffffffu, l0, 1);
    l0 += __shfl_xor_sync(0xffffffffu, l0, 2);
    l1 += __shfl_xor_sync(0xffffffffu, l1, 1);
    l1 += __shfl_xor_sync(0xffffffffu, l1, 2);
    float inv0 = 1.f / l0, inv1 = 1.f / l1;
    __half* op0 = o + headoff + (size_t)row0 * Cdim;
    __half* op1 = o + headoff + (size_t)row1 * Cdim;
#pragma unroll
    for (int d = 0; d < 16; ++d) {
        int col = d * 8 + 2 * t;
        *(__half2*)(op0 + col) = __floats2half2_rn(oacc[d][0] * inv0, oacc[d][1] * inv0);
        *(__half2*)(op1 + col) = __floats2half2_rn(oacc[d][2] * inv1, oacc[d][3] * inv1);
    }
}

// ============================================================================
// Launch
// ============================================================================
extern "C" void kernel_launch(void* const* d_in, const int* in_sizes, int n_in,
                              void* d_out, int out_size)
{
    const float* x  = (const float*)d_in[0];
    const float* Wq = (const float*)d_in[1];
    const float* bq = (const float*)d_in[2];
    const float* Wk = (const float*)d_in[3];
    const float* bk = (const float*)d_in[4];
    const float* Wv = (const float*)d_in[5];
    const float* bv = (const float*)d_in[6];
    const float* Wo = (const float*)d_in[7];
    const float* bo = (const float*)d_in[8];
    float* out = (float*)d_out;

    __half *qp, *kp, *vp, *op, *xh, *wh, *wto;
    cudaGetSymbolAddress((void**)&qp, g_q);
    cudaGetSymbolAddress((void**)&kp, g_k);
    cudaGetSymbolAddress((void**)&vp, g_v);
    cudaGetSymbolAddress((void**)&op, g_o);
    cudaGetSymbolAddress((void**)&xh, g_xh);
    cudaGetSymbolAddress((void**)&wh, g_wh);
    cudaGetSymbolAddress((void**)&wto, g_wto);

    cudaFuncSetAttribute(gemm_qkv_kernel,
                         cudaFuncAttributeMaxDynamicSharedMemorySize, GEMM_SMEM);
    cudaFuncSetAttribute(gemm_o_kernel,
                         cudaFuncAttributeMaxDynamicSharedMemorySize, GEMM_SMEM);
    cudaFuncSetAttribute(attn_mma_kernel,
                         cudaFuncAttributeMaxDynamicSharedMemorySize, ATTN_SMEM_BYTES);

    dim3 gc(SLICE / 1024, 1, 5);           // x (2 slices) + Wq/Wk/Wv
    conv_h_k<<<gc, 256>>>(x, Wq, Wk, Wv, xh, wh);
    dim3 tb(32, 8), tg(Cdim / 32, Cdim / 32);
    transpose_h_k<<<tg, tb>>>(Wo, wto);    // Wo only

    dim3 gq(Cdim / GBN, Mrows / GBM, 3);   // (16, 32, 3)
    gemm_qkv_kernel<<<gq, GTH, GEMM_SMEM>>>(xh, wh, bq, bk, bv, qp, kp, vp);

    dim3 ga(Tseq / ABQ, Hh, Bsz);          // (16, 16, 2)
    attn_mma_kernel<<<ga, 256, ATTN_SMEM_BYTES>>>(qp, kp, vp, op);

    dim3 go(Cdim / GBN, Mrows / GBM);      // (16, 32)
    gemm_o_kernel<<<go, GTH, GEMM_SMEM>>>(op, wto, bo, out);
}

// round 17
// speedup vs baseline: 1.0187x; 1.0187x over previous
#include <cuda_runtime.h>
#include <cuda_fp16.h>
#include <math.h>
#include <stdint.h>

// Problem constants
#define Bsz  2
#define Tseq 2048
#define Cdim 2048
#define Hh   16
#define Dh   128
#define Mrows (Bsz*Tseq)   // 4096
#define SLICE ((size_t)Cdim * Cdim)

// -------- scratch (device globals; no allocation allowed) --------
__device__ __half g_q[(size_t)Mrows * Cdim];
__device__ __half g_k[(size_t)Mrows * Cdim];
__device__ __half g_v[(size_t)Mrows * Cdim];
__device__ __half g_o[(size_t)Mrows * Cdim];
__device__ __half g_xh[(size_t)Mrows * Cdim];       // fp16 x
__device__ __half g_wh[4 * SLICE];                  // fp16 weights (UNtransposed)

// ============================================================================
// Helpers
// ============================================================================
__device__ __forceinline__ uint32_t smem_u32(const void* p) {
    uint32_t a;
    asm("{ .reg .u64 t; cvta.to.shared.u64 t, %1; cvt.u32.u64 %0, t; }"
        : "=r"(a) : "l"(p));
    return a;
}

#define CP16(sa, ga) \
    asm volatile("cp.async.cg.shared.global [%0], [%1], 16;" \
                 :: "r"(sa), "l"(ga) : "memory")

#define MMA_F16(c, a0, a1, a2, a3, b0, b1) \
    asm volatile("mma.sync.aligned.m16n8k16.row.col.f32.f16.f16.f32 " \
        "{%0,%1,%2,%3},{%4,%5,%6,%7},{%8,%9},{%0,%1,%2,%3};" \
        : "+f"((c)[0]), "+f"((c)[1]), "+f"((c)[2]), "+f"((c)[3]) \
        : "r"(a0), "r"(a1), "r"(a2), "r"(a3), "r"(b0), "r"(b1))

#define LDSM4(r0, r1, r2, r3, addr) \
    asm volatile("ldmatrix.sync.aligned.m8n8.x4.shared.b16 {%0,%1,%2,%3}, [%4];" \
        : "=r"(r0), "=r"(r1), "=r"(r2), "=r"(r3) : "r"(addr))

#define LDSM4T(r0, r1, r2, r3, addr) \
    asm volatile("ldmatrix.sync.aligned.m8n8.x4.trans.shared.b16 {%0,%1,%2,%3}, [%4];" \
        : "=r"(r0), "=r"(r1), "=r"(r2), "=r"(r3) : "r"(addr))

#define SW(r) ((((r) >> 2) & 1) << 2)

__device__ __forceinline__ uint32_t pack_h2(float lo, float hi) {
    __half2 h = __floats2half2_rn(lo, hi);
    return *reinterpret_cast<uint32_t*>(&h);
}

// ============================================================================
// fp32 -> fp16 conversion for x (2 slices) + 4 weights, one launch (z 0..5)
// ============================================================================
__global__ __launch_bounds__(256) void conv_h_k(
    const float* __restrict__ x,
    const float* __restrict__ Wq, const float* __restrict__ Wk,
    const float* __restrict__ Wv, const float* __restrict__ Wo,
    __half* __restrict__ xh, __half* __restrict__ wh)
{
    const int z = blockIdx.z;
    const float* src;
    __half* dst;
    if      (z == 0) { src = x;          dst = xh; }
    else if (z == 1) { src = x + SLICE;  dst = xh + SLICE; }
    else if (z == 2) { src = Wq;         dst = wh; }
    else if (z == 3) { src = Wk;         dst = wh + SLICE; }
    else if (z == 4) { src = Wv;         dst = wh + 2 * SLICE; }
    else             { src = Wo;         dst = wh + 3 * SLICE; }
    size_t i = ((size_t)blockIdx.x * 256 + threadIdx.x) * 4;
    float4 v = *(const float4*)(src + i);
    *(__half2*)(dst + i)     = __floats2half2_rn(v.x, v.y);
    *(__half2*)(dst + i + 2) = __floats2half2_rn(v.z, v.w);
}

// ============================================================================
// fp16 mma.sync GEMM (R14 proven): C = A @ W + bias, W UNtransposed [K,N].
// B-frags via ldmatrix.trans. CTA 128x128, BK=64, 3-stage, 8 warps, 2 CTAs/SM.
// ============================================================================
#define GBM 128
#define GBN 128
#define GBK 64
#define NST 3
#define GTH 256
#define A_U32 (GBM * GBK / 2)              // 4096
#define B_U32 (GBK * GBN / 2)              // 4096
#define STAGE_U32 (A_U32 + B_U32)          // 8192
#define STAGE_BYTES (STAGE_U32 * 4)        // 32768
#define GEMM_SMEM (NST * STAGE_BYTES)      // 98304

template<typename OutT>
__device__ __forceinline__ void gemm_body_h(
    const __half* __restrict__ A, const __half* __restrict__ W,
    const float* __restrict__ bias, OutT* __restrict__ Cm,
    uint32_t smbase)
{
    const int tid  = threadIdx.x;
    const int lane = tid & 31;
    const int wid  = tid >> 5;
    const int wm   = wid >> 2;
    const int wn   = wid & 3;
    const int m0   = blockIdx.y * GBM;
    const int n0   = blockIdx.x * GBN;
    const int g    = lane >> 2;
    const int t    = lane & 3;
    const int l15  = lane & 15;

    uint32_t offA[4];
#pragma unroll
    for (int mi = 0; mi < 4; ++mi) {
        int r = wm * 64 + mi * 16 + l15;
        int c = lane >> 4;
        offA[mi] = 4u * (uint32_t)(r * 8 + ((c << 2) ^ SW(r)));
    }
    uint32_t offBT;
    {
        int p = lane >> 4;
        offBT = 4u * (uint32_t)(l15 * 8 + ((p << 2) ^ SW(l15)));
    }

    float acc[4][4][4];
#pragma unroll
    for (int mi = 0; mi < 4; ++mi)
#pragma unroll
        for (int ni = 0; ni < 4; ++ni)
#pragma unroll
            for (int x = 0; x < 4; ++x) acc[mi][ni][x] = 0.f;

    auto load_stage = [&](int s, int k0) {
        uint32_t ab = smbase + (uint32_t)s * STAGE_BYTES;
        uint32_t bb = ab + A_U32 * 4;
        const __half* Ap = A + (size_t)m0 * Cdim + k0;
        const __half* Wp = W + (size_t)k0 * Cdim + n0;
#pragma unroll
        for (int i = 0; i < 4; ++i) {          // A: 128 rows x 8 chunks
            int lin = i * GTH + tid;
            int r   = lin >> 3;
            int cu  = (lin & 7) * 4;
            uint32_t off = 4u * (uint32_t)((cu >> 3) * 1024 + r * 8 + ((cu & 7) ^ SW(r)));
            CP16(ab + off, Ap + (size_t)r * Cdim + cu * 2);
        }
#pragma unroll
        for (int i = 0; i < 4; ++i) {          // W: 64 k-rows x 16 chunks
            int lin = i * GTH + tid;
            int r   = lin >> 4;
            int cu  = (lin & 15) * 4;
            uint32_t off = 4u * (uint32_t)((cu >> 3) * 512 + r * 8 + ((cu & 7) ^ SW(r)));
            CP16(bb + off, Wp + (size_t)r * Cdim + cu * 2);
        }
    };

    load_stage(0, 0);
    asm volatile("cp.async.commit_group;" ::: "memory");
    load_stage(1, GBK);
    asm volatile("cp.async.commit_group;" ::: "memory");

    const int NIT = Cdim / GBK;            // 32
    for (int it = 0; it < NIT; ++it) {
        asm volatile("cp.async.wait_group 1;" ::: "memory");
        __syncthreads();

        const int nx = it + 2;
        if (nx < NIT) load_stage(nx % NST, nx * GBK);
        asm volatile("cp.async.commit_group;" ::: "memory");

        uint32_t abase = smbase + (uint32_t)(it % NST) * STAGE_BYTES;
        uint32_t bbase = abase + A_U32 * 4;

#pragma unroll
        for (int ks = 0; ks < 4; ++ks) {
            uint32_t a[4][4], b[2][4];
#pragma unroll
            for (int mi = 0; mi < 4; ++mi)
                LDSM4(a[mi][0], a[mi][1], a[mi][2], a[mi][3],
                      abase + ks * 4096 + offA[mi]);
#pragma unroll
            for (int j = 0; j < 2; ++j) {
                int dj = wn * 2 + j;
                LDSM4T(b[j][0], b[j][1], b[j][2], b[j][3],
                       bbase + dj * 2048 + ks * 512 + offBT);
            }
#pragma unroll
            for (int mi = 0; mi < 4; ++mi)
#pragma unroll
                for (int j = 0; j < 2; ++j) {
                    MMA_F16(acc[mi][2 * j],     a[mi][0], a[mi][1], a[mi][2], a[mi][3],
                            b[j][0], b[j][1]);
                    MMA_F16(acc[mi][2 * j + 1], a[mi][0], a[mi][1], a[mi][2], a[mi][3],
                            b[j][2], b[j][3]);
                }
        }
    }

#pragma unroll
    for (int mi = 0; mi < 4; ++mi) {
        int r0 = m0 + wm * 64 + mi * 16 + g;
#pragma unroll
        for (int ni = 0; ni < 4; ++ni) {
            int col = n0 + wn * 32 + ni * 8 + 2 * t;
            float2 bb = *(const float2*)(bias + col);
            float v0 = acc[mi][ni][0] + bb.x, v1 = acc[mi][ni][1] + bb.y;
            float v2 = acc[mi][ni][2] + bb.x, v3 = acc[mi][ni][3] + bb.y;
            if (sizeof(OutT) == 2) {
                __half* C = (__half*)Cm;
                *(__half2*)(C + (size_t)r0 * Cdim + col)       = __floats2half2_rn(v0, v1);
                *(__half2*)(C + (size_t)(r0 + 8) * Cdim + col) = __floats2half2_rn(v2, v3);
            } else {
                float* C = (float*)Cm;
                *(float2*)(C + (size_t)r0 * Cdim + col)       = make_float2(v0, v1);
                *(float2*)(C + (size_t)(r0 + 8) * Cdim + col) = make_float2(v2, v3);
            }
        }
    }
}

__global__ __launch_bounds__(GTH, 2) void gemm_qkv_kernel(
    const __half* __restrict__ A, const __half* __restrict__ WhBase,
    const float* __restrict__ bq, const float* __restrict__ bk,
    const float* __restrict__ bv,
    __half* __restrict__ Cq, __half* __restrict__ Ck, __half* __restrict__ Cv)
{
    extern __shared__ uint32_t smu[];
    const int z = blockIdx.z;
    const __half* Wz  = WhBase + (size_t)z * SLICE;
    const float* bias = (z == 0) ? bq : (z == 1) ? bk : bv;
    __half*      Cm   = (z == 0) ? Cq : (z == 1) ? Ck : Cv;
    gemm_body_h<__half>(A, Wz, bias, Cm, smem_u32(smu));
}

__global__ __launch_bounds__(GTH, 2) void gemm_o_kernel(
    const __half* __restrict__ A, const __half* __restrict__ Wz,
    const float* __restrict__ bias, float* __restrict__ Cm)
{
    extern __shared__ uint32_t smu[];
    gemm_body_h<float>(A, Wz, bias, Cm, smem_u32(smu));
}

// ============================================================================
// fp16 flash attention: ABK=128, hoisted Q frags, register P, ldmatrix.trans V,
// exp2 softmax, deferred l. NEW: mask only on diagonal tile; incremental ALiBi.
// CTA: 128 queries, 8 warps. smem 163840 B, 1 CTA/SM.
// ============================================================================
#define ABQ 128
#define ABK 128
#define KS_OFF   8192
#define KS_STRIDE 8192
#define VS_OFF   24576
#define VS_STRIDE 8192
#define ATTN_U32 (VS_OFF + 2 * VS_STRIDE)      // 40960
#define ATTN_SMEM_BYTES (ATTN_U32 * 4)         // 163840

__global__ __launch_bounds__(256, 1) void attn_mma_kernel(
    const __half* __restrict__ q, const __half* __restrict__ k,
    const __half* __restrict__ v, __half* __restrict__ o)
{
    extern __shared__ uint32_t smu[];
    const uint32_t smb = smem_u32(smu);
    const int tid  = threadIdx.x;
    const int lane = tid & 31;
    const int w    = tid >> 5;
    const int g    = lane >> 2;
    const int t    = lane & 3;
    const int l15  = lane & 15;

    const int qbase = (gridDim.x - 1 - blockIdx.x) * ABQ;   // long CTAs first
    const int h = blockIdx.y;
    const int b = blockIdx.z;
    const float LOG2E = 1.4426950408889634f;
    const float scale  = 0.08838834764831845f * LOG2E;
    const float slope  = exp2f(-0.5f * (float)(h + 1)) * LOG2E;
    const float slope8 = slope * 8.f;
    const size_t headoff = (size_t)b * Tseq * Cdim + (size_t)h * Dh;

    // ---- Q tile: 128 rows x 64 u32 ----
    {
        const __half* qp = q + headoff + (size_t)qbase * Cdim;
#pragma unroll
        for (int l = 0; l < 8; ++l) {
            int lin = l * 256 + tid;
            int r   = lin >> 4;
            int cu  = (lin & 15) * 4;
            uint32_t off = (uint32_t)((cu >> 3) * 1024 + r * 8 + ((cu & 7) ^ SW(r)));
            CP16(smb + 4u * off, qp + (size_t)r * Cdim + cu * 2);
        }
    }

    const int ntiles = (qbase >> 7) + 1;

    auto loadKV = [&](int s, int kb) {
        const __half* kp = k + headoff + (size_t)kb * Cdim;
        const __half* vp = v + headoff + (size_t)kb * Cdim;
        uint32_t kbs = smb + 4u * (uint32_t)(KS_OFF + s * KS_STRIDE);
        uint32_t vbs = smb + 4u * (uint32_t)(VS_OFF + s * VS_STRIDE);
#pragma unroll
        for (int l = 0; l < 8; ++l) {
            int lin = l * 256 + tid;
            int r   = lin >> 4;
            int cu  = (lin & 15) * 4;
            uint32_t off = 4u * (uint32_t)((cu >> 3) * 1024 + r * 8 + ((cu & 7) ^ SW(r)));
            CP16(kbs + off, kp + (size_t)r * Cdim + cu * 2);
            CP16(vbs + off, vp + (size_t)r * Cdim + cu * 2);
        }
    };
    loadKV(0, 0);
    asm volatile("cp.async.commit_group;" ::: "memory");

    uint32_t offQ;
    {
        int r = w * 16 + l15;
        int c = lane >> 4;
        offQ = 4u * (uint32_t)(r * 8 + ((c << 2) ^ SW(r)));
    }
    uint32_t offK[8];
#pragma unroll
    for (int nj = 0; nj < 8; ++nj) {
        int r = nj * 16 + ((lane >> 4) << 3) + (lane & 7);
        int c = (lane >> 3) & 1;
        offK[nj] = 4u * (uint32_t)(r * 8 + ((c << 2) ^ SW(r)));
    }
    uint32_t offV;
    {
        int p = lane >> 4;
        offV = 4u * (uint32_t)(l15 * 8 + ((p << 2) ^ SW(l15)));
    }

    asm volatile("cp.async.wait_group 0;" ::: "memory");
    __syncthreads();
    uint32_t qa[8][4];
#pragma unroll
    for (int ks = 0; ks < 8; ++ks)
        LDSM4(qa[ks][0], qa[ks][1], qa[ks][2], qa[ks][3], smb + ks * 4096 + offQ);

    float oacc[16][4];
#pragma unroll
    for (int i = 0; i < 16; ++i)
#pragma unroll
        for (int x = 0; x < 4; ++x) oacc[i][x] = 0.f;

    float mprev0 = -INFINITY, mprev1 = -INFINITY;
    float l0 = 0.f, l1 = 0.f;
    const int row0 = qbase + w * 16 + g;
    const int row1 = row0 + 8;

    for (int kt = 0; kt < ntiles; ++kt) {
        const int sk = kt & 1;
        const int kbase = kt * ABK;
        const uint32_t kbs = smb + 4u * (uint32_t)(KS_OFF + sk * KS_STRIDE);
        const uint32_t vbs = smb + 4u * (uint32_t)(VS_OFF + sk * VS_STRIDE);

        if (kt + 1 < ntiles) {
            loadKV(sk ^ 1, kbase + ABK);
            asm volatile("cp.async.commit_group;" ::: "memory");
        }

        // ---- S = Q K^T ----
        float sacc[16][4];
#pragma unroll
        for (int ni = 0; ni < 16; ++ni)
#pragma unroll
            for (int x = 0; x < 4; ++x) sacc[ni][x] = 0.f;

#pragma unroll
        for (int ks = 0; ks < 8; ++ks) {
#pragma unroll
            for (int nj = 0; nj < 8; ++nj) {
                uint32_t b0, b1, b2, b3;
                LDSM4(b0, b1, b2, b3, kbs + ks * 4096 + offK[nj]);
                MMA_F16(sacc[2 * nj],     qa[ks][0], qa[ks][1], qa[ks][2], qa[ks][3], b0, b1);
                MMA_F16(sacc[2 * nj + 1], qa[ks][0], qa[ks][1], qa[ks][2], qa[ks][3], b2, b3);
            }
        }

        // ---- scale(+log2e) + ALiBi; causal mask only on diagonal tile ----
        const float ab = slope * (float)(kbase + 2 * t - (Tseq - 1));
        float mt0 = -INFINITY, mt1 = -INFINITY;
        if (kt == ntiles - 1) {
#pragma unroll
            for (int ni = 0; ni < 16; ++ni) {
                int col = kbase + ni * 8 + 2 * t;
                float al0 = fmaf((float)ni, slope8, ab);
                float al1 = al0 + slope;
                float v0 = sacc[ni][0] * scale + al0;
                float v1 = sacc[ni][1] * scale + al1;
                float v2 = sacc[ni][2] * scale + al0;
                float v3 = sacc[ni][3] * scale + al1;
                if (col     > row0) v0 = -1e30f;
                if (col + 1 > row0) v1 = -1e30f;
                if (col     > row1) v2 = -1e30f;
                if (col + 1 > row1) v3 = -1e30f;
                sacc[ni][0] = v0; sacc[ni][1] = v1; sacc[ni][2] = v2; sacc[ni][3] = v3;
                mt0 = fmaxf(mt0, fmaxf(v0, v1));
                mt1 = fmaxf(mt1, fmaxf(v2, v3));
            }
        } else {
#pragma unroll
            for (int ni = 0; ni < 16; ++ni) {
                float al0 = fmaf((float)ni, slope8, ab);
                float al1 = al0 + slope;
                float v0 = sacc[ni][0] * scale + al0;
                float v1 = sacc[ni][1] * scale + al1;
                float v2 = sacc[ni][2] * scale + al0;
                float v3 = sacc[ni][3] * scale + al1;
                sacc[ni][0] = v0; sacc[ni][1] = v1; sacc[ni][2] = v2; sacc[ni][3] = v3;
                mt0 = fmaxf(mt0, fmaxf(v0, v1));
                mt1 = fmaxf(mt1, fmaxf(v2, v3));
            }
        }
        mt0 = fmaxf(mt0, __shfl_xor_sync(0xffffffffu, mt0, 1));
        mt0 = fmaxf(mt0, __shfl_xor_sync(0xffffffffu, mt0, 2));
        mt1 = fmaxf(mt1, __shfl_xor_sync(0xffffffffu, mt1, 1));
        mt1 = fmaxf(mt1, __shfl_xor_sync(0xffffffffu, mt1, 2));
        float mnew0 = fmaxf(mprev0, mt0);
        float mnew1 = fmaxf(mprev1, mt1);
        float corr0 = exp2f(mprev0 - mnew0);
        float corr1 = exp2f(mprev1 - mnew1);
        float sum0 = 0.f, sum1 = 0.f;
#pragma unroll
        for (int ni = 0; ni < 16; ++ni) {
            float p0 = exp2f(sacc[ni][0] - mnew0);
            float p1 = exp2f(sacc[ni][1] - mnew0);
            float p2 = exp2f(sacc[ni][2] - mnew1);
            float p3 = exp2f(sacc[ni][3] - mnew1);
            sum0 += p0 + p1; sum1 += p2 + p3;
            sacc[ni][0] = p0; sacc[ni][1] = p1; sacc[ni][2] = p2; sacc[ni][3] = p3;
        }
        l0 = l0 * corr0 + sum0;
        l1 = l1 * corr1 + sum1;
        mprev0 = mnew0; mprev1 = mnew1;
#pragma unroll
        for (int i = 0; i < 16; ++i) {
            oacc[i][0] *= corr0; oacc[i][1] *= corr0;
            oacc[i][2] *= corr1; oacc[i][3] *= corr1;
        }

        // ---- O += P V ----
#pragma unroll
        for (int ks = 0; ks < 8; ++ks) {
            uint32_t pa0 = pack_h2(sacc[2 * ks][0],     sacc[2 * ks][1]);
            uint32_t pa1 = pack_h2(sacc[2 * ks][2],     sacc[2 * ks][3]);
            uint32_t pa2 = pack_h2(sacc[2 * ks + 1][0], sacc[2 * ks + 1][1]);
            uint32_t pa3 = pack_h2(sacc[2 * ks + 1][2], sacc[2 * ks + 1][3]);
#pragma unroll
            for (int dj = 0; dj < 8; ++dj) {
                uint32_t b0, b1, b2, b3;
                LDSM4T(b0, b1, b2, b3, vbs + dj * 4096 + ks * 512 + offV);
                MMA_F16(oacc[2 * dj],     pa0, pa1, pa2, pa3, b0, b1);
                MMA_F16(oacc[2 * dj + 1], pa0, pa1, pa2, pa3, b2, b3);
            }
        }

        if (kt + 1 < ntiles) {
            asm volatile("cp.async.wait_group 0;" ::: "memory");
            __syncthreads();
        }
    }

    // ---- epilogue: reduce deferred l, normalize, store ----
    l0 += __shfl_xor_sync(0xffffffffu, l0, 1);
    l0 += __shfl_xor_sync(0xffffffffu, l0, 2);
    l1 += __shfl_xor_sync(0xffffffffu, l1, 1);
    l1 += __shfl_xor_sync(0xffffffffu, l1, 2);
    float inv0 = 1.f / l0, inv1 = 1.f / l1;
    __half* op0 = o + headoff + (size_t)row0 * Cdim;
    __half* op1 = o + headoff + (size_t)row1 * Cdim;
#pragma unroll
    for (int d = 0; d < 16; ++d) {
        int col = d * 8 + 2 * t;
        *(__half2*)(op0 + col) = __floats2half2_rn(oacc[d][0] * inv0, oacc[d][1] * inv0);
        *(__half2*)(op1 + col) = __floats2half2_rn(oacc[d][2] * inv1, oacc[d][3] * inv1);
    }
}

// ============================================================================
// Launch
// ============================================================================
extern "C" void kernel_launch(void* const* d_in, const int* in_sizes, int n_in,
                              void* d_out, int out_size)
{
    const float* x  = (const float*)d_in[0];
    const float* Wq = (const float*)d_in[1];
    const float* bq = (const float*)d_in[2];
    const float* Wk = (const float*)d_in[3];
    const float* bk = (const float*)d_in[4];
    const float* Wv = (const float*)d_in[5];
    const float* bv = (const float*)d_in[6];
    const float* Wo = (const float*)d_in[7];
    const float* bo = (const float*)d_in[8];
    float* out = (float*)d_out;

    __half *qp, *kp, *vp, *op, *xh, *wh;
    cudaGetSymbolAddress((void**)&qp, g_q);
    cudaGetSymbolAddress((void**)&kp, g_k);
    cudaGetSymbolAddress((void**)&vp, g_v);
    cudaGetSymbolAddress((void**)&op, g_o);
    cudaGetSymbolAddress((void**)&xh, g_xh);
    cudaGetSymbolAddress((void**)&wh, g_wh);
    __half* who = wh + 3 * SLICE;

    cudaFuncSetAttribute(gemm_qkv_kernel,
                         cudaFuncAttributeMaxDynamicSharedMemorySize, GEMM_SMEM);
    cudaFuncSetAttribute(gemm_o_kernel,
                         cudaFuncAttributeMaxDynamicSharedMemorySize, GEMM_SMEM);
    cudaFuncSetAttribute(attn_mma_kernel,
                         cudaFuncAttributeMaxDynamicSharedMemorySize, ATTN_SMEM_BYTES);

    dim3 gc(SLICE / 1024, 1, 6);           // x (2 slices) + 4 weights
    conv_h_k<<<gc, 256>>>(x, Wq, Wk, Wv, Wo, xh, wh);

    dim3 gq(Cdim / GBN, Mrows / GBM, 3);   // (16, 32, 3)
    gemm_qkv_kernel<<<gq, GTH, GEMM_SMEM>>>(xh, wh, bq, bk, bv, qp, kp, vp);

    dim3 ga(Tseq / ABQ, Hh, Bsz);          // (16, 16, 2)
    attn_mma_kernel<<<ga, 256, ATTN_SMEM_BYTES>>>(qp, kp, vp, op);

    dim3 go(Cdim / GBN, Mrows / GBM);      // (16, 32)
    gemm_o_kernel<<<go, GTH, GEMM_SMEM>>>(op, who, bo, out);
}